// round 8
// baseline (speedup 1.0000x reference)
#include <cuda_runtime.h>

#define MAXN 100000
#define F 64

// Scratch (allocation-free rule: __device__ globals). Referenced ONLY in
// device code — host-side address-of on GB300 (ATS) silently routes traffic
// over NVLink-C2C (34x slowdown, R6 lesson).
__device__ int   g_degi[MAXN];
__device__ float g_dinv[MAXN];
__device__ float g_hs1[(size_t)MAXN * F];
__device__ float g_acc1[(size_t)MAXN * F];
__device__ float g_hs2[(size_t)MAXN * F];
__device__ float g_acc2[(size_t)MAXN * F];

template <int L> __device__ __forceinline__ const float* hs_in()  { return L == 1 ? g_hs1 : g_hs2; }
template <int L> __device__ __forceinline__ float*       acc_rw() { return L == 1 ? g_acc1 : g_acc2; }

__global__ void k_deg_init(int N) {
    int i = blockIdx.x * blockDim.x + threadIdx.x;
    if (i < N) g_degi[i] = 0;
}

__global__ void k_deg_count(const int* __restrict__ dst, int E) {
    int e = blockIdx.x * blockDim.x + threadIdx.x;
    if (e < E) atomicAdd(&g_degi[dst[e]], 1);
}

__global__ void k_dinv(int N) {
    int i = blockIdx.x * blockDim.x + threadIdx.x;
    if (i < N) g_dinv[i] = rsqrtf(1.0f + (float)g_degi[i]);  // +1 self-loop
}

// Scatter: acc[dst] += hs[src].  acc pre-initialized to hs (self term) by the
// producing GEMM; dinv[src] folded into hs; dinv[dst] applied by consumer.
template <int L>
__global__ void k_scatter(const int* __restrict__ src, const int* __restrict__ dst, int E) {
    const float* hs = hs_in<L>();
    float* acc = acc_rw<L>();
    int t = blockIdx.x * blockDim.x + threadIdx.x;
    int e = t >> 4;
    if (e >= E) return;
    int c = t & 15;
    int s = src[e];
    int d = dst[e];
    float4 v = *(const float4*)&hs[(size_t)s * F + c * 4];
    float* p = &acc[(size_t)d * F + c * 4];
    asm volatile("red.global.add.v4.f32 [%0], {%1,%2,%3,%4};"
                 :: "l"(p), "f"(v.x), "f"(v.y), "f"(v.z), "f"(v.w)
                 : "memory");
}

// Register-blocked fused GEMM: each thread computes a TM(4)-row x TN(16)-col
// tile -> each smem weight chunk is reused across 4 rows (smem B/FMA 4x lower
// than the row-per-thread version, which was smem-pipe-bound at 56us).
//  MODE 0: in = x[row];                 g_hs1 = g_acc1 = (in@W)*dinv
//  MODE 1: in = relu(dinv*g_acc1 + b);  g_hs2 = g_acc2 = (in@W)*dinv
//  MODE 2: in = relu(dinv*g_acc2 + b);  out = in@W + b_out   (NOUT=32)
template <int NOUT, int MODE>
__global__ void __launch_bounds__(256, 2)
k_gemm(const float* __restrict__ xin, const float* __restrict__ W,
       const float* __restrict__ b_in, const float* __restrict__ b_out,
       float* __restrict__ out, int N) {
    constexpr int TM = 4, TN = 16;
    constexpr int CPT = NOUT / TN;          // column splits per row (4 or 2)
    constexpr int RPB = (256 / CPT) * TM;   // rows per block (256 or 512)

    __shared__ float sW[F * NOUT];
    {
        const float4* W4 = (const float4*)W;
        float4* sW4 = (float4*)sW;
        for (int i = threadIdx.x; i < F * NOUT / 4; i += 256) sW4[i] = W4[i];
    }
    __syncthreads();

    int q = threadIdx.x % CPT;              // which TN-wide column slice
    int g = threadIdx.x / CPT;              // row group within block
    int row0 = blockIdx.x * RPB + g * TM;
    if (row0 >= N) return;

    float acc[TM][TN];
#pragma unroll
    for (int r = 0; r < TM; r++)
#pragma unroll
        for (int j = 0; j < TN; j++) acc[r][j] = 0.0f;

    float dv[TM];
#pragma unroll
    for (int r = 0; r < TM; r++) {
        int row = row0 + r;
        dv[r] = (row < N) ? g_dinv[row] : 0.0f;
    }

    const float* srcbuf = (MODE == 0) ? xin : ((MODE == 1) ? (const float*)g_acc1
                                                           : (const float*)g_acc2);
    const float4* b4 = (const float4*)b_in;

#pragma unroll
    for (int kk = 0; kk < F / 4; kk++) {
        float xr[TM][4];
#pragma unroll
        for (int r = 0; r < TM; r++) {
            int row = row0 + r;
            float4 a = make_float4(0.f, 0.f, 0.f, 0.f);
            if (row < N) a = *(const float4*)&srcbuf[(size_t)row * F + kk * 4];
            if (MODE == 0) {
                xr[r][0] = a.x; xr[r][1] = a.y; xr[r][2] = a.z; xr[r][3] = a.w;
            } else {
                float4 bb = b4[kk];
                xr[r][0] = fmaxf(fmaf(dv[r], a.x, bb.x), 0.0f);
                xr[r][1] = fmaxf(fmaf(dv[r], a.y, bb.y), 0.0f);
                xr[r][2] = fmaxf(fmaf(dv[r], a.z, bb.z), 0.0f);
                xr[r][3] = fmaxf(fmaf(dv[r], a.w, bb.w), 0.0f);
            }
        }
#pragma unroll
        for (int u = 0; u < 4; u++) {
            const float4* wr = (const float4*)&sW[(kk * 4 + u) * NOUT + q * TN];
            float4 w0 = wr[0], w1 = wr[1], w2 = wr[2], w3 = wr[3];
#pragma unroll
            for (int r = 0; r < TM; r++) {
                float v = xr[r][u];
                acc[r][0]  = fmaf(v, w0.x, acc[r][0]);
                acc[r][1]  = fmaf(v, w0.y, acc[r][1]);
                acc[r][2]  = fmaf(v, w0.z, acc[r][2]);
                acc[r][3]  = fmaf(v, w0.w, acc[r][3]);
                acc[r][4]  = fmaf(v, w1.x, acc[r][4]);
                acc[r][5]  = fmaf(v, w1.y, acc[r][5]);
                acc[r][6]  = fmaf(v, w1.z, acc[r][6]);
                acc[r][7]  = fmaf(v, w1.w, acc[r][7]);
                acc[r][8]  = fmaf(v, w2.x, acc[r][8]);
                acc[r][9]  = fmaf(v, w2.y, acc[r][9]);
                acc[r][10] = fmaf(v, w2.z, acc[r][10]);
                acc[r][11] = fmaf(v, w2.w, acc[r][11]);
                acc[r][12] = fmaf(v, w3.x, acc[r][12]);
                acc[r][13] = fmaf(v, w3.y, acc[r][13]);
                acc[r][14] = fmaf(v, w3.z, acc[r][14]);
                acc[r][15] = fmaf(v, w3.w, acc[r][15]);
            }
        }
    }

    if (MODE == 2) {
        const float4* bo4 = (const float4*)(b_out + q * TN);
#pragma unroll
        for (int r = 0; r < TM; r++) {
            int row = row0 + r;
            if (row >= N) break;
            float4* o4 = (float4*)(out + (size_t)row * NOUT + q * TN);
#pragma unroll
            for (int j = 0; j < TN / 4; j++) {
                float4 bo = bo4[j];
                float4 rr;
                rr.x = acc[r][4 * j + 0] + bo.x;
                rr.y = acc[r][4 * j + 1] + bo.y;
                rr.z = acc[r][4 * j + 2] + bo.z;
                rr.w = acc[r][4 * j + 3] + bo.w;
                o4[j] = rr;
            }
        }
    } else {
        float* hsw  = (MODE == 0) ? g_hs1 : g_hs2;
        float* accw = (MODE == 0) ? g_acc1 : g_acc2;
#pragma unroll
        for (int r = 0; r < TM; r++) {
            int row = row0 + r;
            if (row >= N) break;
            float4* hw4 = (float4*)(hsw  + (size_t)row * F + q * TN);
            float4* aw4 = (float4*)(accw + (size_t)row * F + q * TN);
#pragma unroll
            for (int j = 0; j < TN / 4; j++) {
                float4 rr;
                rr.x = acc[r][4 * j + 0] * dv[r];
                rr.y = acc[r][4 * j + 1] * dv[r];
                rr.z = acc[r][4 * j + 2] * dv[r];
                rr.w = acc[r][4 * j + 3] * dv[r];
                hw4[j] = rr;
                aw4[j] = rr;  // acc starts at self-contribution; scatter adds on top
            }
        }
    }
}

extern "C" void kernel_launch(void* const* d_in, const int* in_sizes, int n_in,
                              void* d_out, int out_size) {
    const float* x  = (const float*)d_in[0];
    const int*   ei = (const int*)d_in[1];
    const float* W1 = (const float*)d_in[2];
    const float* b1 = (const float*)d_in[3];
    const float* W2 = (const float*)d_in[4];
    const float* b2 = (const float*)d_in[5];
    const float* Wl = (const float*)d_in[6];
    const float* bl = (const float*)d_in[7];
    float* out = (float*)d_out;

    int N = in_sizes[0] / F;
    int E = in_sizes[1] / 2;
    const int* src = ei;
    const int* dst = ei + E;

    int nb256 = (N + 255) / 256;
    int eb = (E + 255) / 256;
    long long st = (long long)E * 16;
    int sb = (int)((st + 255) / 256);

    int gb64 = (N + 255) / 256;   // k_gemm<64,*>: 256 rows per block
    int gb32 = (N + 511) / 512;   // k_gemm<32,2>: 512 rows per block

    // degree + dinv
    k_deg_init<<<nb256, 256>>>(N);
    k_deg_count<<<eb, 256>>>(dst, E);
    k_dinv<<<nb256, 256>>>(N);

    // layer 1: hs1 = acc1 = (x@W1)*dinv ; scatter into acc1
    k_gemm<F, 0><<<gb64, 256>>>(x, W1, nullptr, nullptr, nullptr, N);
    k_scatter<1><<<sb, 256>>>(src, dst, E);

    // layer 2: in = relu(dinv*acc1 + b1); hs2 = acc2 = (in@W2)*dinv ; scatter into acc2
    k_gemm<F, 1><<<gb64, 256>>>(nullptr, W2, b1, nullptr, nullptr, N);
    k_scatter<2><<<sb, 256>>>(src, dst, E);

    // head: in = relu(dinv*acc2 + b2); out = in@Wl + bl
    k_gemm<32, 2><<<gb32, 256>>>(nullptr, Wl, b2, bl, out, N);
}

// round 10
// speedup vs baseline: 1.5056x; 1.5056x over previous
#include <cuda_runtime.h>

#define MAXN 100000
#define MAXE 1000000
#define F 64

// Scratch (__device__ globals only; never take their address in host code —
// GB300 ATS silently routes host-shadow addresses over NVLink-C2C, R6 lesson).
__device__ int   g_degi[MAXN];
__device__ int   g_pre[MAXN];
__device__ int   g_bsum[256];
__device__ int   g_rowptr[MAXN];
__device__ int   g_cursor[MAXN];
__device__ int   g_csrc[MAXE];
__device__ float g_dinv[MAXN];
__device__ float g_hs1[(size_t)MAXN * F];
__device__ float g_acc1[(size_t)MAXN * F];
__device__ float g_hs2[(size_t)MAXN * F];
__device__ float g_acc2[(size_t)MAXN * F];

__global__ void k_deg_init(int N) {
    int i = blockIdx.x * blockDim.x + threadIdx.x;
    if (i < N) g_degi[i] = 0;
}

__global__ void k_deg_count(const int* __restrict__ dst, int E) {
    int e = blockIdx.x * blockDim.x + threadIdx.x;
    if (e < E) atomicAdd(&g_degi[dst[e]], 1);
}

__global__ void k_dinv(int N) {
    int i = blockIdx.x * blockDim.x + threadIdx.x;
    if (i < N) g_dinv[i] = rsqrtf(1.0f + (float)g_degi[i]);  // +1 self-loop
}

// ---- CSR build: blockwise inclusive scan of degrees -> rowptr ----
__global__ void k_scan1(int N) {
    __shared__ int s[512];
    int t = threadIdx.x;
    int i = blockIdx.x * 512 + t;
    s[t] = (i < N) ? g_degi[i] : 0;
    __syncthreads();
#pragma unroll
    for (int o = 1; o < 512; o <<= 1) {
        int a = (t >= o) ? s[t - o] : 0;
        __syncthreads();
        s[t] += a;
        __syncthreads();
    }
    if (i < N) g_pre[i] = s[t];
    if (t == 511) g_bsum[blockIdx.x] = s[511];
}

__global__ void k_scan2(int NB) {  // single block; NB <= 256
    __shared__ int s[256];
    int t = threadIdx.x;
    s[t] = (t < NB) ? g_bsum[t] : 0;
    __syncthreads();
#pragma unroll
    for (int o = 1; o < 256; o <<= 1) {
        int a = (t >= o) ? s[t - o] : 0;
        __syncthreads();
        s[t] += a;
        __syncthreads();
    }
    if (t < NB) g_bsum[t] = s[t];
}

__global__ void k_scan3(int N) {
    int i = blockIdx.x * blockDim.x + threadIdx.x;
    if (i >= N) return;
    int b = i >> 9;
    int off = b ? g_bsum[b - 1] : 0;
    int start = off + g_pre[i] - g_degi[i];  // exclusive prefix
    g_rowptr[i] = start;
    g_cursor[i] = start;
}

__global__ void k_fill(const int* __restrict__ src, const int* __restrict__ dst, int E) {
    int e = blockIdx.x * blockDim.x + threadIdx.x;
    if (e >= E) return;
    int p = atomicAdd(&g_cursor[dst[e]], 1);
    g_csrc[p] = src[e];
}

// ---- Gather: acc[n] = hs[n] (self) + sum_{s in neigh(n)} hs[s] ----
// hs is 25.6MB -> fully L2-resident, so neighbor reads are L2 hits.
// 16 threads per node, float4 each -> one 256B row per node, coalesced write.
template <int L>
__global__ void k_gather(int N) {
    const float* hs = (L == 1) ? g_hs1 : g_hs2;
    float* acc = (L == 1) ? g_acc1 : g_acc2;
    int t = blockIdx.x * blockDim.x + threadIdx.x;
    int node = t >> 4;
    if (node >= N) return;
    int c = (t & 15) * 4;
    float4 a = *(const float4*)&hs[(size_t)node * F + c];
    int rp = g_rowptr[node];
    int de = g_degi[node];
    for (int j = 0; j < de; j++) {
        int s = g_csrc[rp + j];  // uniform across the 16 lanes -> broadcast
        float4 v = *(const float4*)&hs[(size_t)s * F + c];
        a.x += v.x; a.y += v.y; a.z += v.z; a.w += v.w;
    }
    *(float4*)&acc[(size_t)node * F + c] = a;
}

// ---- Fused GEMM: TM=4 rows x TN=8 cols per thread -> 1.5 B/FMA L1 traffic
// (under the 2 B/FMA smem-crossbar budget), 32 accumulators -> ~70 regs.
//  MODE 0: in = x[row];                 g_hs1 = (in@W)*dinv
//  MODE 1: in = relu(dinv*g_acc1 + b);  g_hs2 = (in@W)*dinv
//  MODE 2: in = relu(dinv*g_acc2 + b);  out = in@W + b_out   (NOUT=32)
template <int NOUT, int MODE>
__global__ void __launch_bounds__(256, 3)
k_gemm(const float* __restrict__ xin, const float* __restrict__ W,
       const float* __restrict__ b_in, const float* __restrict__ b_out,
       float* __restrict__ out, int N) {
    constexpr int TM = 4, TN = 8;
    constexpr int CPT = NOUT / TN;          // col slices per row (8 or 4)
    constexpr int RPB = (256 / CPT) * TM;   // rows per block (128 or 256)

    __shared__ float sW[F * NOUT];
    __shared__ float sB[F];
    {
        const float4* W4 = (const float4*)W;
        float4* sW4 = (float4*)sW;
        for (int i = threadIdx.x; i < F * NOUT / 4; i += 256) sW4[i] = W4[i];
        if (MODE != 0 && threadIdx.x < F) sB[threadIdx.x] = b_in[threadIdx.x];
    }
    __syncthreads();

    int q  = threadIdx.x % CPT;
    int gl = threadIdx.x / CPT;
    int row0 = blockIdx.x * RPB + gl * TM;
    if (row0 >= N) return;

    float acc[TM][TN];
#pragma unroll
    for (int r = 0; r < TM; r++)
#pragma unroll
        for (int j = 0; j < TN; j++) acc[r][j] = 0.0f;

    float dv[TM];
#pragma unroll
    for (int r = 0; r < TM; r++) {
        int row = row0 + r;
        dv[r] = (row < N) ? g_dinv[row] : 0.0f;
    }

    const float* srcbuf = (MODE == 0) ? xin
                        : (MODE == 1) ? (const float*)g_acc1
                                      : (const float*)g_acc2;

#pragma unroll
    for (int kk = 0; kk < F / 4; kk++) {
        float xr[TM][4];
#pragma unroll
        for (int r = 0; r < TM; r++) {
            int row = row0 + r;
            float4 a = make_float4(0.f, 0.f, 0.f, 0.f);
            if (row < N) a = *(const float4*)&srcbuf[(size_t)row * F + kk * 4];
            if (MODE == 0) {
                xr[r][0] = a.x; xr[r][1] = a.y; xr[r][2] = a.z; xr[r][3] = a.w;
            } else {
                float4 bb = *(const float4*)&sB[kk * 4];
                xr[r][0] = fmaxf(fmaf(dv[r], a.x, bb.x), 0.0f);
                xr[r][1] = fmaxf(fmaf(dv[r], a.y, bb.y), 0.0f);
                xr[r][2] = fmaxf(fmaf(dv[r], a.z, bb.z), 0.0f);
                xr[r][3] = fmaxf(fmaf(dv[r], a.w, bb.w), 0.0f);
            }
        }
#pragma unroll
        for (int u = 0; u < 4; u++) {
            const float4* wr = (const float4*)&sW[(kk * 4 + u) * NOUT + q * TN];
            float4 w0 = wr[0], w1 = wr[1];
#pragma unroll
            for (int r = 0; r < TM; r++) {
                float v = xr[r][u];
                acc[r][0] = fmaf(v, w0.x, acc[r][0]);
                acc[r][1] = fmaf(v, w0.y, acc[r][1]);
                acc[r][2] = fmaf(v, w0.z, acc[r][2]);
                acc[r][3] = fmaf(v, w0.w, acc[r][3]);
                acc[r][4] = fmaf(v, w1.x, acc[r][4]);
                acc[r][5] = fmaf(v, w1.y, acc[r][5]);
                acc[r][6] = fmaf(v, w1.z, acc[r][6]);
                acc[r][7] = fmaf(v, w1.w, acc[r][7]);
            }
        }
    }

    if (MODE == 2) {
        const float4* bo4 = (const float4*)(b_out + q * TN);
        float4 bo0 = bo4[0], bo1 = bo4[1];
#pragma unroll
        for (int r = 0; r < TM; r++) {
            int row = row0 + r;
            if (row >= N) break;
            float4* o4 = (float4*)(out + (size_t)row * NOUT + q * TN);
            float4 r0, r1;
            r0.x = acc[r][0] + bo0.x;  r0.y = acc[r][1] + bo0.y;
            r0.z = acc[r][2] + bo0.z;  r0.w = acc[r][3] + bo0.w;
            r1.x = acc[r][4] + bo1.x;  r1.y = acc[r][5] + bo1.y;
            r1.z = acc[r][6] + bo1.z;  r1.w = acc[r][7] + bo1.w;
            o4[0] = r0; o4[1] = r1;
        }
    } else {
        float* hsw = (MODE == 0) ? g_hs1 : g_hs2;
#pragma unroll
        for (int r = 0; r < TM; r++) {
            int row = row0 + r;
            if (row >= N) break;
            float4* h4 = (float4*)(hsw + (size_t)row * F + q * TN);
            float4 r0, r1;
            r0.x = acc[r][0] * dv[r];  r0.y = acc[r][1] * dv[r];
            r0.z = acc[r][2] * dv[r];  r0.w = acc[r][3] * dv[r];
            r1.x = acc[r][4] * dv[r];  r1.y = acc[r][5] * dv[r];
            r1.z = acc[r][6] * dv[r];  r1.w = acc[r][7] * dv[r];
            h4[0] = r0; h4[1] = r1;
        }
    }
}

extern "C" void kernel_launch(void* const* d_in, const int* in_sizes, int n_in,
                              void* d_out, int out_size) {
    const float* x  = (const float*)d_in[0];
    const int*   ei = (const int*)d_in[1];
    const float* W1 = (const float*)d_in[2];
    const float* b1 = (const float*)d_in[3];
    const float* W2 = (const float*)d_in[4];
    const float* b2 = (const float*)d_in[5];
    const float* Wl = (const float*)d_in[6];
    const float* bl = (const float*)d_in[7];
    float* out = (float*)d_out;

    int N = in_sizes[0] / F;
    int E = in_sizes[1] / 2;
    const int* src = ei;
    const int* dst = ei + E;

    int nb256 = (N + 255) / 256;
    int eb    = (E + 255) / 256;
    int nbs   = (N + 511) / 512;          // scan blocks (196 for N=100k)
    int gb64  = (N + 127) / 128;          // k_gemm<64,*>
    int gb32  = (N + 255) / 256;          // k_gemm<32,2>
    int gab   = (N * 16 + 255) / 256;     // gather: 16 threads/node

    // degree + CSR + dinv (recomputed each launch; deterministic work)
    k_deg_init<<<nb256, 256>>>(N);
    k_deg_count<<<eb, 256>>>(dst, E);
    k_scan1<<<nbs, 512>>>(N);
    k_scan2<<<1, 256>>>(nbs);
    k_scan3<<<nb256, 256>>>(N);
    k_dinv<<<nb256, 256>>>(N);
    k_fill<<<eb, 256>>>(src, dst, E);

    // layer 1: hs1 = (x@W1)*dinv ; acc1 = hs1 + gather(hs1)
    k_gemm<F, 0><<<gb64, 256>>>(x, W1, nullptr, nullptr, nullptr, N);
    k_gather<1><<<gab, 256>>>(N);

    // layer 2: in = relu(dinv*acc1 + b1); hs2 = (in@W2)*dinv ; acc2 = gather
    k_gemm<F, 1><<<gb64, 256>>>(nullptr, W2, b1, nullptr, nullptr, N);
    k_gather<2><<<gab, 256>>>(N);

    // head: in = relu(dinv*acc2 + b2); out = in@Wl + bl
    k_gemm<32, 2><<<gb32, 256>>>(nullptr, Wl, b2, bl, out, N);
}

// round 11
// speedup vs baseline: 1.6695x; 1.1089x over previous
#include <cuda_runtime.h>

#define MAXN 100000
#define MAXE 1000000
#define F 64

// Scratch (__device__ globals only; never take their address in host code —
// GB300 ATS silently routes host-shadow addresses over NVLink-C2C, R6 lesson).
__device__ int   g_degi[MAXN];
__device__ int   g_pre[MAXN];
__device__ int   g_bsum[256];
__device__ int   g_rowptr[MAXN];
__device__ int   g_cursor[MAXN];
__device__ int   g_csrc[MAXE];
__device__ float g_dinv[MAXN];
__device__ float g_hs1[(size_t)MAXN * F];
__device__ float g_acc1[(size_t)MAXN * F];
__device__ float g_hs2[(size_t)MAXN * F];
__device__ float g_acc2[(size_t)MAXN * F];

__global__ void k_deg_init(int N) {
    int i = blockIdx.x * blockDim.x + threadIdx.x;
    if (i < N) g_degi[i] = 0;
}

__global__ void k_deg_count(const int* __restrict__ dst, int E) {
    int e = blockIdx.x * blockDim.x + threadIdx.x;
    if (e < E) atomicAdd(&g_degi[dst[e]], 1);
}

__global__ void k_dinv(int N) {
    int i = blockIdx.x * blockDim.x + threadIdx.x;
    if (i < N) g_dinv[i] = rsqrtf(1.0f + (float)g_degi[i]);  // +1 self-loop
}

// ---- CSR build: blockwise inclusive scan of degrees -> rowptr ----
__global__ void k_scan1(int N) {
    __shared__ int s[512];
    int t = threadIdx.x;
    int i = blockIdx.x * 512 + t;
    s[t] = (i < N) ? g_degi[i] : 0;
    __syncthreads();
#pragma unroll
    for (int o = 1; o < 512; o <<= 1) {
        int a = (t >= o) ? s[t - o] : 0;
        __syncthreads();
        s[t] += a;
        __syncthreads();
    }
    if (i < N) g_pre[i] = s[t];
    if (t == 511) g_bsum[blockIdx.x] = s[511];
}

// Fused scan2+scan3: each block reduces bsum[0..b-1] itself (<=256 ints),
// then writes rowptr/cursor. Removes the serial single-block scan2 kernel.
__global__ void k_scan23(int N, int NB) {
    __shared__ int red[512];
    int b = blockIdx.x;
    int t = threadIdx.x;
    red[t] = (t < b && t < NB) ? g_bsum[t] : 0;
    __syncthreads();
#pragma unroll
    for (int o = 256; o > 0; o >>= 1) {
        if (t < o) red[t] += red[t + o];
        __syncthreads();
    }
    int off = red[0];
    int i = b * 512 + t;
    if (i < N) {
        int start = off + g_pre[i] - g_degi[i];  // exclusive prefix
        g_rowptr[i] = start;
        g_cursor[i] = start;
    }
}

__global__ void k_fill(const int* __restrict__ src, const int* __restrict__ dst, int E) {
    int e = blockIdx.x * blockDim.x + threadIdx.x;
    if (e >= E) return;
    int p = atomicAdd(&g_cursor[dst[e]], 1);
    g_csrc[p] = src[e];
}

// ---- Gather: acc[n] = hs[n] (self) + sum_{s in neigh(n)} hs[s] ----
// hs is 25.6MB -> L2-resident. 16 threads/node, float4 each; neighbor loop
// unrolled x2 for MLP.
template <int L>
__global__ void k_gather(int N) {
    const float* hs = (L == 1) ? g_hs1 : g_hs2;
    float* acc = (L == 1) ? g_acc1 : g_acc2;
    int t = blockIdx.x * blockDim.x + threadIdx.x;
    int node = t >> 4;
    if (node >= N) return;
    int c = (t & 15) * 4;
    float4 a = *(const float4*)&hs[(size_t)node * F + c];
    int rp = g_rowptr[node];
    int de = g_degi[node];
    int j = 0;
    for (; j + 1 < de; j += 2) {
        int s0 = g_csrc[rp + j];
        int s1 = g_csrc[rp + j + 1];
        float4 v0 = *(const float4*)&hs[(size_t)s0 * F + c];
        float4 v1 = *(const float4*)&hs[(size_t)s1 * F + c];
        a.x += v0.x; a.y += v0.y; a.z += v0.z; a.w += v0.w;
        a.x += v1.x; a.y += v1.y; a.z += v1.z; a.w += v1.w;
    }
    if (j < de) {
        int s0 = g_csrc[rp + j];
        float4 v0 = *(const float4*)&hs[(size_t)s0 * F + c];
        a.x += v0.x; a.y += v0.y; a.z += v0.z; a.w += v0.w;
    }
    *(float4*)&acc[(size_t)node * F + c] = a;
}

// ---- Fused GEMM: TM=4 rows x TN=8 cols per thread -> 1.5 B/FMA L1 traffic
// (under the 2 B/FMA smem-crossbar budget), 32 accumulators.
//  MODE 0: in = x[row];                 g_hs1 = (in@W)*dinv
//  MODE 1: in = relu(dinv*g_acc1 + b);  g_hs2 = (in@W)*dinv
//  MODE 2: in = relu(dinv*g_acc2 + b);  out = in@W + b_out   (NOUT=32)
template <int NOUT, int MODE>
__global__ void __launch_bounds__(256, 3)
k_gemm(const float* __restrict__ xin, const float* __restrict__ W,
       const float* __restrict__ b_in, const float* __restrict__ b_out,
       float* __restrict__ out, int N) {
    constexpr int TM = 4, TN = 8;
    constexpr int CPT = NOUT / TN;          // col slices per row (8 or 4)
    constexpr int RPB = (256 / CPT) * TM;   // rows per block (128 or 256)

    __shared__ float sW[F * NOUT];
    __shared__ float sB[F];
    {
        const float4* W4 = (const float4*)W;
        float4* sW4 = (float4*)sW;
        for (int i = threadIdx.x; i < F * NOUT / 4; i += 256) sW4[i] = W4[i];
        if (MODE != 0 && threadIdx.x < F) sB[threadIdx.x] = b_in[threadIdx.x];
    }
    __syncthreads();

    int q  = threadIdx.x % CPT;
    int gl = threadIdx.x / CPT;
    int row0 = blockIdx.x * RPB + gl * TM;
    if (row0 >= N) return;

    float acc[TM][TN];
#pragma unroll
    for (int r = 0; r < TM; r++)
#pragma unroll
        for (int j = 0; j < TN; j++) acc[r][j] = 0.0f;

    float dv[TM];
#pragma unroll
    for (int r = 0; r < TM; r++) {
        int row = row0 + r;
        dv[r] = (row < N) ? g_dinv[row] : 0.0f;
    }

    const float* srcbuf = (MODE == 0) ? xin
                        : (MODE == 1) ? (const float*)g_acc1
                                      : (const float*)g_acc2;

#pragma unroll
    for (int kk = 0; kk < F / 4; kk++) {
        float xr[TM][4];
#pragma unroll
        for (int r = 0; r < TM; r++) {
            int row = row0 + r;
            float4 a = make_float4(0.f, 0.f, 0.f, 0.f);
            if (row < N) a = *(const float4*)&srcbuf[(size_t)row * F + kk * 4];
            if (MODE == 0) {
                xr[r][0] = a.x; xr[r][1] = a.y; xr[r][2] = a.z; xr[r][3] = a.w;
            } else {
                float4 bb = *(const float4*)&sB[kk * 4];
                xr[r][0] = fmaxf(fmaf(dv[r], a.x, bb.x), 0.0f);
                xr[r][1] = fmaxf(fmaf(dv[r], a.y, bb.y), 0.0f);
                xr[r][2] = fmaxf(fmaf(dv[r], a.z, bb.z), 0.0f);
                xr[r][3] = fmaxf(fmaf(dv[r], a.w, bb.w), 0.0f);
            }
        }
#pragma unroll
        for (int u = 0; u < 4; u++) {
            const float4* wr = (const float4*)&sW[(kk * 4 + u) * NOUT + q * TN];
            float4 w0 = wr[0], w1 = wr[1];
#pragma unroll
            for (int r = 0; r < TM; r++) {
                float v = xr[r][u];
                acc[r][0] = fmaf(v, w0.x, acc[r][0]);
                acc[r][1] = fmaf(v, w0.y, acc[r][1]);
                acc[r][2] = fmaf(v, w0.z, acc[r][2]);
                acc[r][3] = fmaf(v, w0.w, acc[r][3]);
                acc[r][4] = fmaf(v, w1.x, acc[r][4]);
                acc[r][5] = fmaf(v, w1.y, acc[r][5]);
                acc[r][6] = fmaf(v, w1.z, acc[r][6]);
                acc[r][7] = fmaf(v, w1.w, acc[r][7]);
            }
        }
    }

    if (MODE == 2) {
        const float4* bo4 = (const float4*)(b_out + q * TN);
        float4 bo0 = bo4[0], bo1 = bo4[1];
#pragma unroll
        for (int r = 0; r < TM; r++) {
            int row = row0 + r;
            if (row >= N) break;
            float4* o4 = (float4*)(out + (size_t)row * NOUT + q * TN);
            float4 r0, r1;
            r0.x = acc[r][0] + bo0.x;  r0.y = acc[r][1] + bo0.y;
            r0.z = acc[r][2] + bo0.z;  r0.w = acc[r][3] + bo0.w;
            r1.x = acc[r][4] + bo1.x;  r1.y = acc[r][5] + bo1.y;
            r1.z = acc[r][6] + bo1.z;  r1.w = acc[r][7] + bo1.w;
            o4[0] = r0; o4[1] = r1;
        }
    } else {
        float* hsw = (MODE == 0) ? g_hs1 : g_hs2;
#pragma unroll
        for (int r = 0; r < TM; r++) {
            int row = row0 + r;
            if (row >= N) break;
            float4* h4 = (float4*)(hsw + (size_t)row * F + q * TN);
            float4 r0, r1;
            r0.x = acc[r][0] * dv[r];  r0.y = acc[r][1] * dv[r];
            r0.z = acc[r][2] * dv[r];  r0.w = acc[r][3] * dv[r];
            r1.x = acc[r][4] * dv[r];  r1.y = acc[r][5] * dv[r];
            r1.z = acc[r][6] * dv[r];  r1.w = acc[r][7] * dv[r];
            h4[0] = r0; h4[1] = r1;
        }
    }
}

extern "C" void kernel_launch(void* const* d_in, const int* in_sizes, int n_in,
                              void* d_out, int out_size) {
    const float* x  = (const float*)d_in[0];
    const int*   ei = (const int*)d_in[1];
    const float* W1 = (const float*)d_in[2];
    const float* b1 = (const float*)d_in[3];
    const float* W2 = (const float*)d_in[4];
    const float* b2 = (const float*)d_in[5];
    const float* Wl = (const float*)d_in[6];
    const float* bl = (const float*)d_in[7];
    float* out = (float*)d_out;

    int N = in_sizes[0] / F;
    int E = in_sizes[1] / 2;
    const int* src = ei;
    const int* dst = ei + E;

    int nb256 = (N + 255) / 256;
    int eb    = (E + 255) / 256;
    int nbs   = (N + 511) / 512;          // scan blocks (196 for N=100k)
    int gb64  = (N + 127) / 128;          // k_gemm<64,*>
    int gb32  = (N + 255) / 256;          // k_gemm<32,2>
    int gab   = (N * 16 + 255) / 256;     // gather: 16 threads/node

    // Fork/join stream for overlapping CSR build with gemm1. Created fresh
    // each call (no static guards) and intentionally not destroyed — a forked
    // stream can't be destroyed while its origin stream is mid-capture, and
    // kernel_launch is only invoked a handful of times per process.
    cudaStream_t s2;
    cudaStreamCreateWithFlags(&s2, cudaStreamNonBlocking);
    cudaEvent_t evDeg, evCsr;
    cudaEventCreateWithFlags(&evDeg, cudaEventDisableTiming);
    cudaEventCreateWithFlags(&evCsr, cudaEventDisableTiming);

    // degree (needed by BOTH branches)
    k_deg_init<<<nb256, 256>>>(N);
    k_deg_count<<<eb, 256>>>(dst, E);
    cudaEventRecord(evDeg, 0);

    // branch A (stream s2): CSR build — consumed first by gather1
    cudaStreamWaitEvent(s2, evDeg, 0);
    k_scan1<<<nbs, 512, 0, s2>>>(N);
    k_scan23<<<nbs, 512, 0, s2>>>(N, nbs);
    k_fill<<<eb, 256, 0, s2>>>(src, dst, E);
    cudaEventRecord(evCsr, s2);

    // branch B (main stream): dinv + gemm1 (needs only degree)
    k_dinv<<<nb256, 256>>>(N);
    k_gemm<F, 0><<<gb64, 256>>>(x, W1, nullptr, nullptr, nullptr, N);

    // join: gather1 needs CSR + hs1
    cudaStreamWaitEvent(0, evCsr, 0);
    k_gather<1><<<gab, 256>>>(N);

    // layer 2: in = relu(dinv*acc1 + b1); hs2 = (in@W2)*dinv ; gather
    k_gemm<F, 1><<<gb64, 256>>>(nullptr, W2, b1, nullptr, nullptr, N);
    k_gather<2><<<gab, 256>>>(N);

    // head: in = relu(dinv*acc2 + b2); out = in@Wl + bl
    k_gemm<32, 2><<<gb32, 256>>>(nullptr, Wl, b2, bl, out, N);
}